// round 13
// baseline (speedup 1.0000x reference)
#include <cuda_runtime.h>
#include <cuda_fp16.h>
#include <cstdint>

#define IN_F   4096
#define OUT_F  4096
#define PACKED (IN_F / 2)
#define NBLK   (IN_F / 64)

#define BM 128
#define BN 128
#define BK 64                        // fp16: 128x64 halfs = 16 KB per block
#define NKT (IN_F / BK)              // 64 k-tiles
#define TILE_U32 4096                // uint32s per operand block (16 KB)
#define STAGE_BYTES  32768           // A (16KB) + B (16KB)
#define STAGES 3
#define SMEM_HDR 1024
#define SMEM_BYTES (SMEM_HDR + STAGES * STAGE_BYTES)   // 99328 B -> 2 CTA/SM

#define WBLOCKS (OUT_F * (PACKED / 4) / 256)           // 8192 dequant blocks

// Fragment-ordered fp16 operand scratch (each uint32 = half2{k, k+1}).
// A block (128m x 64k): u32 idx = (kk*8 + mf)*128 + lane*4 + slot
//   lane = (rr&7)*4 + kpair, slot = (rr>>3) + 2*hi   (m=mf*16+rr, k=kk*16+hi*8+kpair*2)
// B block (128n x 64k): u32 idx = (kk*16 + nf)*64 + lane*2 + hi
//   lane = (n&7)*4 + kpair                            (n=nf*8+(n&7))
__device__ uint32_t g_At[(size_t)(8192 / BM) * NKT * TILE_U32];   // 67 MB
__device__ uint32_t g_Bt[(size_t)(OUT_F / BN) * NKT * TILE_U32];  // 33.5 MB

#define MBAR_INIT(a, c) \
    asm volatile("mbarrier.init.shared.b64 [%0], %1;" :: "r"(a), "r"((uint32_t)(c)) : "memory")
#define MBAR_EXPECT_TX(a, b) \
    asm volatile("mbarrier.arrive.expect_tx.shared.b64 _, [%0], %1;" :: "r"(a), "r"((uint32_t)(b)) : "memory")
#define MBAR_WAIT(a, ph) do {                                                    \
    uint32_t _done = 0;                                                          \
    while (!_done)                                                               \
        asm volatile("{\n\t.reg .pred p;\n\t"                                    \
            "mbarrier.try_wait.parity.shared.b64 p, [%1], %2;\n\t"               \
            "selp.b32 %0, 1, 0, p;\n\t}"                                         \
            : "=r"(_done) : "r"((uint32_t)(a)), "r"((uint32_t)(ph)) : "memory"); \
    } while (0)
#define BULK_G2S(dst, src, bytes, mbar) \
    asm volatile("cp.async.bulk.shared::cluster.global.mbarrier::complete_tx::bytes " \
                 "[%0], [%1], %2, [%3];" \
                 :: "r"((uint32_t)(dst)), "l"(src), "r"((uint32_t)(bytes)), \
                    "r"((uint32_t)(mbar)) : "memory")

__device__ __forceinline__ uint32_t pack_h2(float lo, float hi) {
    half2 h = __floats2half2_rn(lo, hi);
    return *reinterpret_cast<uint32_t*>(&h);
}

// ---------------------------------------------------------------------------
// Merged pre-pass: blocks [0, WBLOCKS) dequantize W -> g_Bt; the rest
// fp16-round + retile X -> g_At. Independent jobs run concurrently.
// ---------------------------------------------------------------------------
__global__ void prepass_kernel(const int4* __restrict__ wp4,
                               const float* __restrict__ centroids,
                               const float* __restrict__ scales,
                               const float* __restrict__ X, int M) {
    if (blockIdx.x < WBLOCKS) {
        __shared__ float cent[16];
        if (threadIdx.x < 16) cent[threadIdx.x] = centroids[threadIdx.x];
        __syncthreads();

        int idx = blockIdx.x * blockDim.x + threadIdx.x;   // over OUT_F * 512
        int o = idx >> 9;               // row (n)
        int t = idx & 511;              // int4 index; k0 = 8t

        int4 w = wp4[idx];
        float s = scales[o * NBLK + (t >> 3)];

        int b0 = w.x & 255, b1 = w.y & 255, b2 = w.z & 255, b3 = w.w & 255;
        float e0 = cent[b0 >> 4] * s, e1 = cent[b0 & 15] * s;
        float e2 = cent[b1 >> 4] * s, e3 = cent[b1 & 15] * s;
        float e4 = cent[b2 >> 4] * s, e5 = cent[b2 & 15] * s;
        float e6 = cent[b3 >> 4] * s, e7 = cent[b3 & 15] * s;

        int ntile = o >> 7;
        int np = o & 127;
        int kt = t >> 3;                // (8t)/64
        int kk = (t & 7) >> 1;          // 16-k group
        int hi = t & 1;                 // low/high 8-k half
        int nf = np >> 3;
        int l0 = (np & 7) * 4;

        uint32_t* base = g_Bt + (size_t)ntile * (NKT * TILE_U32)
                              + (size_t)kt * TILE_U32 + (kk * 16 + nf) * 64 + l0 * 2 + hi;
        base[0] = pack_h2(e0, e1);      // kpair 0
        base[2] = pack_h2(e2, e3);      // kpair 1
        base[4] = pack_h2(e4, e5);      // kpair 2
        base[6] = pack_h2(e6, e7);      // kpair 3
    } else {
        int t = (blockIdx.x - WBLOCKS) * blockDim.x + threadIdx.x;
        if (t >= M * (IN_F / 4)) return;
        int e = t * 4;
        int m = e >> 12;
        int i = e & (IN_F - 1);

        float4 v = *reinterpret_cast<const float4*>(X + (size_t)m * IN_F + i);

        int mtile = m >> 7;
        int mp = m & 127;
        int mf = mp >> 4;
        int rr = mp & 15;
        int kt = i >> 6;
        int kp = i & 63;
        int kk = kp >> 4;
        int kw = kp & 15;
        int hi = kw >> 3;
        int c0 = (kw & 7) >> 1;         // 0 or 2
        int s  = ((rr >> 3) & 1) + 2 * hi;
        int l0 = (rr & 7) * 4 + c0;

        uint32_t* base = g_At + (size_t)mtile * (NKT * TILE_U32) + (size_t)kt * TILE_U32
                              + (kk * 8 + mf) * 128 + l0 * 4 + s;
        base[0] = pack_h2(v.x, v.y);
        base[4] = pack_h2(v.z, v.w);    // next lane -> +4 u32
    }
}

// ---------------------------------------------------------------------------
// GEMM: 128x128x64 tiles, 4 warps (2x2, warp tile 64x64), mma.sync fp16
// m16n8k16 fp32-accum, 2 CTA/SM. Bulk-async producer + mbarrier ring;
// only warp 0 polls the mbarrier, others gate on __syncthreads.
// ---------------------------------------------------------------------------
__device__ __forceinline__ void mma_fp16(float* c, const uint32_t* a, const uint32_t* b) {
    asm volatile(
        "mma.sync.aligned.m16n8k16.row.col.f32.f16.f16.f32 "
        "{%0,%1,%2,%3}, {%4,%5,%6,%7}, {%8,%9}, {%0,%1,%2,%3};\n"
        : "+f"(c[0]), "+f"(c[1]), "+f"(c[2]), "+f"(c[3])
        : "r"(a[0]), "r"(a[1]), "r"(a[2]), "r"(a[3]),
          "r"(b[0]), "r"(b[1]));
}

__device__ __forceinline__ void load_frags(uint32_t a[4][4], uint32_t b[8][2],
                                           const uint32_t* A0, const uint32_t* B0,
                                           int kk, int wm, int wn, int lane) {
#pragma unroll
    for (int ma = 0; ma < 4; ma++) {
        const uint4 v = *reinterpret_cast<const uint4*>(
            A0 + (kk * 8 + wm * 4 + ma) * 128 + lane * 4);
        a[ma][0] = v.x; a[ma][1] = v.y; a[ma][2] = v.z; a[ma][3] = v.w;
    }
#pragma unroll
    for (int nb = 0; nb < 8; nb++) {
        const uint2 v = *reinterpret_cast<const uint2*>(
            B0 + (kk * 16 + wn * 8 + nb) * 64 + lane * 2);
        b[nb][0] = v.x; b[nb][1] = v.y;
    }
}

__global__ void __launch_bounds__(128, 2)
gemm_fp16_kernel(float* __restrict__ Out) {
    extern __shared__ uint32_t smem[];

    const int tid  = threadIdx.x;
    const int warp = tid >> 5;
    const int lane = tid & 31;
    const int wm = warp >> 1;              // 0..1 -> M offset wm*64
    const int wn = warp & 1;               // 0..1 -> N offset wn*64

    const uint32_t* Ag = g_At + (size_t)blockIdx.y * (NKT * TILE_U32);
    const uint32_t* Bg = g_Bt + (size_t)blockIdx.x * (NKT * TILE_U32);

    const uint32_t sbase = (uint32_t)__cvta_generic_to_shared(smem);
    const uint32_t mb0   = sbase;                 // full[s] at +s*8
    const uint32_t st0   = sbase + SMEM_HDR;
    const uint32_t* stf  = smem + SMEM_HDR / 4;

    if (tid == 0) {
#pragma unroll
        for (int s = 0; s < STAGES; s++) MBAR_INIT(mb0 + s * 8, 1);
    }
    __syncthreads();

    if (tid == 0) {
#pragma unroll
        for (int p = 0; p < 2; p++) {
            MBAR_EXPECT_TX(mb0 + p * 8, STAGE_BYTES);
            BULK_G2S(st0 + p * STAGE_BYTES,         Ag + (size_t)p * TILE_U32, 16384, mb0 + p * 8);
            BULK_G2S(st0 + p * STAGE_BYTES + 16384, Bg + (size_t)p * TILE_U32, 16384, mb0 + p * 8);
        }
    }

    float c[4][8][4];
#pragma unroll
    for (int i = 0; i < 4; i++)
#pragma unroll
        for (int j = 0; j < 8; j++)
#pragma unroll
            for (int k = 0; k < 4; k++) c[i][j][k] = 0.0f;

    uint32_t a[2][4][4];
    uint32_t b[2][8][2];

    for (int kt = 0; kt < NKT; kt++) {
        const int s = kt % STAGES;
        if (warp == 0)
            MBAR_WAIT(mb0 + s * 8, (kt / STAGES) & 1);   // tile kt arrived
        __syncthreads();   // propagates arrival to all warps; old buf free

        const uint32_t* A0 = stf + (size_t)s * (STAGE_BYTES / 4);
        const uint32_t* B0 = A0 + TILE_U32;

        load_frags(a[0], b[0], A0, B0, 0, wm, wn, lane);

        if (tid == 0 && kt + 2 < NKT) {
            const int sn = (kt + 2) % STAGES;
            MBAR_EXPECT_TX(mb0 + sn * 8, STAGE_BYTES);
            BULK_G2S(st0 + sn * STAGE_BYTES,         Ag + (size_t)(kt + 2) * TILE_U32, 16384, mb0 + sn * 8);
            BULK_G2S(st0 + sn * STAGE_BYTES + 16384, Bg + (size_t)(kt + 2) * TILE_U32, 16384, mb0 + sn * 8);
        }

#pragma unroll
        for (int kk = 0; kk < 4; kk++) {
            const int cur = kk & 1;
            if (kk < 3)
                load_frags(a[cur ^ 1], b[cur ^ 1], A0, B0, kk + 1, wm, wn, lane);
#pragma unroll
            for (int ma = 0; ma < 4; ma++)
#pragma unroll
                for (int nb = 0; nb < 8; nb++)
                    mma_fp16(c[ma][nb], a[cur][ma], b[cur][nb]);
        }
    }

    // epilogue
    float* Og = Out + (size_t)blockIdx.y * BM * OUT_F + blockIdx.x * BN;
#pragma unroll
    for (int ma = 0; ma < 4; ma++) {
#pragma unroll
        for (int nb = 0; nb < 8; nb++) {
            int r  = wm * 64 + ma * 16 + (lane >> 2);
            int cc = wn * 64 + nb * 8 + 2 * (lane & 3);
            *reinterpret_cast<float2*>(&Og[(size_t)r * OUT_F + cc]) =
                make_float2(c[ma][nb][0], c[ma][nb][1]);
            *reinterpret_cast<float2*>(&Og[(size_t)(r + 8) * OUT_F + cc]) =
                make_float2(c[ma][nb][2], c[ma][nb][3]);
        }
    }
}

// ---------------------------------------------------------------------------
extern "C" void kernel_launch(void* const* d_in, const int* in_sizes, int n_in,
                              void* d_out, int out_size) {
    const float* x      = (const float*)d_in[0];   // [M, 4096] fp32
    const int*   wp     = (const int*)d_in[1];     // [4096, 2048] int32 bytes
    const float* cent   = (const float*)d_in[2];   // [16]
    const float* scales = (const float*)d_in[3];   // [4096, 64]
    float* out = (float*)d_out;

    const int M = in_sizes[0] / IN_F;              // 8192

    int xblocks = (M * (IN_F / 4) + 255) / 256;    // 32768
    prepass_kernel<<<WBLOCKS + xblocks, 256>>>(
        reinterpret_cast<const int4*>(wp), cent, scales, x, M);

    cudaFuncSetAttribute(gemm_fp16_kernel,
                         cudaFuncAttributeMaxDynamicSharedMemorySize, SMEM_BYTES);
    dim3 grid(OUT_F / BN, M / BM);                 // (32, 64)
    gemm_fp16_kernel<<<grid, 128, SMEM_BYTES>>>(out);
}

// round 14
// speedup vs baseline: 1.0518x; 1.0518x over previous
#include <cuda_runtime.h>
#include <cuda_fp16.h>
#include <cstdint>

#define IN_F   4096
#define OUT_F  4096
#define PACKED (IN_F / 2)
#define NBLK   (IN_F / 64)

#define BM 128
#define BN 128
#define BK 64                        // fp16: 128x64 halfs = 16 KB per block
#define NKT (IN_F / BK)              // 64 k-tiles
#define TILE_U32 4096                // uint32s per operand block (16 KB)
#define STAGE_BYTES  32768           // A (16KB) + B (16KB)
#define STAGES 3
#define SMEM_HDR 1024
#define SMEM_BYTES (SMEM_HDR + STAGES * STAGE_BYTES)   // 99328 B -> 2 CTA/SM

#define WTILES ((OUT_F / BN) * NKT)  // 2048 weight tiles

// Fragment-ordered fp16 operand scratch (each uint32 = half2{k, k+1}).
// A block (128m x 64k): u32 idx = (kk*8 + mf)*128 + lane*4 + slot
//   lane = (rr&7)*4 + kpair, slot = (rr>>3) + 2*hi   (m=mf*16+rr, k=kk*16+hi*8+kpair*2)
// B block (128n x 64k): u32 idx = (kk*16 + nf)*64 + lane*2 + hi
//   lane = (n&7)*4 + kpair                            (n=nf*8+(n&7))
__device__ uint32_t g_At[(size_t)(8192 / BM) * NKT * TILE_U32];   // 67 MB
__device__ uint32_t g_Bt[(size_t)(OUT_F / BN) * NKT * TILE_U32];  // 33.5 MB

#define MBAR_INIT(a, c) \
    asm volatile("mbarrier.init.shared.b64 [%0], %1;" :: "r"(a), "r"((uint32_t)(c)) : "memory")
#define MBAR_EXPECT_TX(a, b) \
    asm volatile("mbarrier.arrive.expect_tx.shared.b64 _, [%0], %1;" :: "r"(a), "r"((uint32_t)(b)) : "memory")
#define MBAR_WAIT(a, ph) do {                                                    \
    uint32_t _done = 0;                                                          \
    while (!_done)                                                               \
        asm volatile("{\n\t.reg .pred p;\n\t"                                    \
            "mbarrier.try_wait.parity.shared.b64 p, [%1], %2;\n\t"               \
            "selp.b32 %0, 1, 0, p;\n\t}"                                         \
            : "=r"(_done) : "r"((uint32_t)(a)), "r"((uint32_t)(ph)) : "memory"); \
    } while (0)
#define BULK_G2S(dst, src, bytes, mbar) \
    asm volatile("cp.async.bulk.shared::cluster.global.mbarrier::complete_tx::bytes " \
                 "[%0], [%1], %2, [%3];" \
                 :: "r"((uint32_t)(dst)), "l"(src), "r"((uint32_t)(bytes)), \
                    "r"((uint32_t)(mbar)) : "memory")

__device__ __forceinline__ uint32_t pack_h2(float lo, float hi) {
    half2 h = __floats2half2_rn(lo, hi);
    return *reinterpret_cast<uint32_t*>(&h);
}

// ---------------------------------------------------------------------------
// Staged prepass: one 128-thread block per 128x64 operand tile.
// Coalesced global read -> fragment-order scatter into SMEM -> coalesced
// contiguous 16KB store. Blocks [0, WTILES): W dequant; rest: X retile.
// ---------------------------------------------------------------------------
__global__ void __launch_bounds__(128)
prepass_kernel(const int4* __restrict__ wp4,
               const float* __restrict__ centroids,
               const float* __restrict__ scales,
               const float* __restrict__ X, int M) {
    __shared__ uint32_t stg[TILE_U32];
    __shared__ float cent[16];
    const int bid = blockIdx.x;
    const int tid = threadIdx.x;

    if (bid < WTILES) {
        if (tid < 16) cent[tid] = centroids[tid];
        __syncthreads();
        const int ntile = bid >> 6;          // / NKT
        const int kt    = bid & (NKT - 1);

#pragma unroll
        for (int j = 0; j < 8; j++) {
            int f   = tid + j * 128;         // 0..1023
            int row = f >> 3;                // n within tile
            int q   = f & 7;                 // int4 within row-tile (8 k-elems)
            int o   = ntile * 128 + row;
            int4 w  = wp4[(size_t)o * (PACKED / 4) + kt * 8 + q];
            float s = scales[o * NBLK + kt]; // one scale block per k-tile

            int b0 = w.x & 255, b1 = w.y & 255, b2 = w.z & 255, b3 = w.w & 255;
            float e0 = cent[b0 >> 4] * s, e1 = cent[b0 & 15] * s;
            float e2 = cent[b1 >> 4] * s, e3 = cent[b1 & 15] * s;
            float e4 = cent[b2 >> 4] * s, e5 = cent[b2 & 15] * s;
            float e6 = cent[b3 >> 4] * s, e7 = cent[b3 & 15] * s;

            int kp0 = q * 8;
            int kk  = kp0 >> 4;
            int hi  = (kp0 & 15) >> 3;
            int nf  = row >> 3;
            int l0  = (row & 7) * 4;
            uint32_t* b = stg + (kk * 16 + nf) * 64 + l0 * 2 + hi;
            b[0] = pack_h2(e0, e1);
            b[2] = pack_h2(e2, e3);
            b[4] = pack_h2(e4, e5);
            b[6] = pack_h2(e6, e7);
        }
        __syncthreads();
        uint4* dst = reinterpret_cast<uint4*>(
            g_Bt + (size_t)ntile * (NKT * TILE_U32) + (size_t)kt * TILE_U32);
        const uint4* src = reinterpret_cast<const uint4*>(stg);
#pragma unroll
        for (int j = 0; j < 8; j++) dst[tid + j * 128] = src[tid + j * 128];
    } else {
        const int b2    = bid - WTILES;
        const int mtile = b2 >> 6;
        const int kt    = b2 & (NKT - 1);

#pragma unroll
        for (int j = 0; j < 16; j++) {
            int f   = tid + j * 128;         // 0..2047
            int row = f >> 4;                // m within tile
            int c4  = f & 15;                // float4 within 64-k row
            float4 v = *reinterpret_cast<const float4*>(
                X + (size_t)(mtile * 128 + row) * IN_F + kt * 64 + c4 * 4);

            int kp = c4 * 4;
            int kk = kp >> 4, kw = kp & 15;
            int hi = kw >> 3;
            int c0 = (kw & 7) >> 1;
            int mf = row >> 4, rr = row & 15;
            int s  = ((rr >> 3) & 1) + 2 * hi;
            int l0 = (rr & 7) * 4 + c0;
            uint32_t* b = stg + (kk * 8 + mf) * 128 + l0 * 4 + s;
            b[0] = pack_h2(v.x, v.y);
            b[4] = pack_h2(v.z, v.w);        // next lane -> +4 u32
        }
        __syncthreads();
        uint4* dst = reinterpret_cast<uint4*>(
            g_At + (size_t)mtile * (NKT * TILE_U32) + (size_t)kt * TILE_U32);
        const uint4* src = reinterpret_cast<const uint4*>(stg);
#pragma unroll
        for (int j = 0; j < 8; j++) dst[tid + j * 128] = src[tid + j * 128];
    }
}

// ---------------------------------------------------------------------------
// GEMM (identical to R12 best): 128x128x64 tiles, 4 warps (2x2, warp tile
// 64x64), mma.sync fp16 m16n8k16 fp32-accum, 2 CTA/SM. Bulk-async producer
// + mbarrier ring, register double-buffered fragments.
// ---------------------------------------------------------------------------
__device__ __forceinline__ void mma_fp16(float* c, const uint32_t* a, const uint32_t* b) {
    asm volatile(
        "mma.sync.aligned.m16n8k16.row.col.f32.f16.f16.f32 "
        "{%0,%1,%2,%3}, {%4,%5,%6,%7}, {%8,%9}, {%0,%1,%2,%3};\n"
        : "+f"(c[0]), "+f"(c[1]), "+f"(c[2]), "+f"(c[3])
        : "r"(a[0]), "r"(a[1]), "r"(a[2]), "r"(a[3]),
          "r"(b[0]), "r"(b[1]));
}

__device__ __forceinline__ void load_frags(uint32_t a[4][4], uint32_t b[8][2],
                                           const uint32_t* A0, const uint32_t* B0,
                                           int kk, int wm, int wn, int lane) {
#pragma unroll
    for (int ma = 0; ma < 4; ma++) {
        const uint4 v = *reinterpret_cast<const uint4*>(
            A0 + (kk * 8 + wm * 4 + ma) * 128 + lane * 4);
        a[ma][0] = v.x; a[ma][1] = v.y; a[ma][2] = v.z; a[ma][3] = v.w;
    }
#pragma unroll
    for (int nb = 0; nb < 8; nb++) {
        const uint2 v = *reinterpret_cast<const uint2*>(
            B0 + (kk * 16 + wn * 8 + nb) * 64 + lane * 2);
        b[nb][0] = v.x; b[nb][1] = v.y;
    }
}

__global__ void __launch_bounds__(128, 2)
gemm_fp16_kernel(float* __restrict__ Out) {
    extern __shared__ uint32_t smem[];

    const int tid  = threadIdx.x;
    const int warp = tid >> 5;
    const int lane = tid & 31;
    const int wm = warp >> 1;              // 0..1 -> M offset wm*64
    const int wn = warp & 1;               // 0..1 -> N offset wn*64

    const uint32_t* Ag = g_At + (size_t)blockIdx.y * (NKT * TILE_U32);
    const uint32_t* Bg = g_Bt + (size_t)blockIdx.x * (NKT * TILE_U32);

    const uint32_t sbase = (uint32_t)__cvta_generic_to_shared(smem);
    const uint32_t mb0   = sbase;                 // full[s] at +s*8
    const uint32_t st0   = sbase + SMEM_HDR;
    const uint32_t* stf  = smem + SMEM_HDR / 4;

    if (tid == 0) {
#pragma unroll
        for (int s = 0; s < STAGES; s++) MBAR_INIT(mb0 + s * 8, 1);
    }
    __syncthreads();

    if (tid == 0) {
#pragma unroll
        for (int p = 0; p < 2; p++) {
            MBAR_EXPECT_TX(mb0 + p * 8, STAGE_BYTES);
            BULK_G2S(st0 + p * STAGE_BYTES,         Ag + (size_t)p * TILE_U32, 16384, mb0 + p * 8);
            BULK_G2S(st0 + p * STAGE_BYTES + 16384, Bg + (size_t)p * TILE_U32, 16384, mb0 + p * 8);
        }
    }

    float c[4][8][4];
#pragma unroll
    for (int i = 0; i < 4; i++)
#pragma unroll
        for (int j = 0; j < 8; j++)
#pragma unroll
            for (int k = 0; k < 4; k++) c[i][j][k] = 0.0f;

    uint32_t a[2][4][4];
    uint32_t b[2][8][2];

    for (int kt = 0; kt < NKT; kt++) {
        const int s = kt % STAGES;
        MBAR_WAIT(mb0 + s * 8, (kt / STAGES) & 1);   // tile kt arrived
        __syncthreads();                             // all done reading buf (kt+2)%3

        const uint32_t* A0 = stf + (size_t)s * (STAGE_BYTES / 4);
        const uint32_t* B0 = A0 + TILE_U32;

        load_frags(a[0], b[0], A0, B0, 0, wm, wn, lane);

        if (tid == 0 && kt + 2 < NKT) {
            const int sn = (kt + 2) % STAGES;
            MBAR_EXPECT_TX(mb0 + sn * 8, STAGE_BYTES);
            BULK_G2S(st0 + sn * STAGE_BYTES,         Ag + (size_t)(kt + 2) * TILE_U32, 16384, mb0 + sn * 8);
            BULK_G2S(st0 + sn * STAGE_BYTES + 16384, Bg + (size_t)(kt + 2) * TILE_U32, 16384, mb0 + sn * 8);
        }

#pragma unroll
        for (int kk = 0; kk < 4; kk++) {
            const int cur = kk & 1;
            if (kk < 3)
                load_frags(a[cur ^ 1], b[cur ^ 1], A0, B0, kk + 1, wm, wn, lane);
#pragma unroll
            for (int ma = 0; ma < 4; ma++)
#pragma unroll
                for (int nb = 0; nb < 8; nb++)
                    mma_fp16(c[ma][nb], a[cur][ma], b[cur][nb]);
        }
    }

    // epilogue
    float* Og = Out + (size_t)blockIdx.y * BM * OUT_F + blockIdx.x * BN;
#pragma unroll
    for (int ma = 0; ma < 4; ma++) {
#pragma unroll
        for (int nb = 0; nb < 8; nb++) {
            int r  = wm * 64 + ma * 16 + (lane >> 2);
            int cc = wn * 64 + nb * 8 + 2 * (lane & 3);
            *reinterpret_cast<float2*>(&Og[(size_t)r * OUT_F + cc]) =
                make_float2(c[ma][nb][0], c[ma][nb][1]);
            *reinterpret_cast<float2*>(&Og[(size_t)(r + 8) * OUT_F + cc]) =
                make_float2(c[ma][nb][2], c[ma][nb][3]);
        }
    }
}

// ---------------------------------------------------------------------------
extern "C" void kernel_launch(void* const* d_in, const int* in_sizes, int n_in,
                              void* d_out, int out_size) {
    const float* x      = (const float*)d_in[0];   // [M, 4096] fp32
    const int*   wp     = (const int*)d_in[1];     // [4096, 2048] int32 bytes
    const float* cent   = (const float*)d_in[2];   // [16]
    const float* scales = (const float*)d_in[3];   // [4096, 64]
    float* out = (float*)d_out;

    const int M = in_sizes[0] / IN_F;              // 8192

    int xtiles = (M / BM) * NKT;                   // 4096
    prepass_kernel<<<WTILES + xtiles, 128>>>(
        reinterpret_cast<const int4*>(wp), cent, scales, x, M);

    cudaFuncSetAttribute(gemm_fp16_kernel,
                         cudaFuncAttributeMaxDynamicSharedMemorySize, SMEM_BYTES);
    dim3 grid(OUT_F / BN, M / BM);                 // (32, 64)
    gemm_fp16_kernel<<<grid, 128, SMEM_BYTES>>>(out);
}

// round 15
// speedup vs baseline: 1.1187x; 1.0637x over previous
#include <cuda_runtime.h>
#include <cuda_fp16.h>
#include <cstdint>

#define IN_F   4096
#define OUT_F  4096
#define PACKED (IN_F / 2)
#define NBLK   (IN_F / 64)

#define BM 128
#define BN 128
#define BK 64                        // fp16: 128x64 halfs = 16 KB per block
#define NKT (IN_F / BK)              // 64 k-tiles
#define TILE_U32 4096                // uint32s per operand block (16 KB)
#define STAGE_BYTES  32768           // A (16KB) + B (16KB)
#define STAGES 3
#define SMEM_HDR 1024
#define SMEM_BYTES (SMEM_HDR + STAGES * STAGE_BYTES)   // 99328 B -> 2 CTA/SM

#define WTILES ((OUT_F / BN) * NKT)  // 2048 weight tiles

// Fragment-ordered fp16 operand scratch (each uint32 = half2{k, k+1}).
// A block (128m x 64k): u32 idx = (kk*8 + mf)*128 + lane*4 + slot
//   lane = (rr&7)*4 + kpair, slot = (rr>>3) + 2*hi   (m=mf*16+rr, k=kk*16+hi*8+kpair*2)
// B block (128n x 64k): u32 idx = (kk*16 + nf)*64 + lane*2 + hi
//   lane = (n&7)*4 + kpair                            (n=nf*8+(n&7))
__device__ uint32_t g_At[(size_t)(8192 / BM) * NKT * TILE_U32];   // 67 MB
__device__ uint32_t g_Bt[(size_t)(OUT_F / BN) * NKT * TILE_U32];  // 33.5 MB

#define MBAR_INIT(a, c) \
    asm volatile("mbarrier.init.shared.b64 [%0], %1;" :: "r"(a), "r"((uint32_t)(c)) : "memory")
#define MBAR_EXPECT_TX(a, b) \
    asm volatile("mbarrier.arrive.expect_tx.shared.b64 _, [%0], %1;" :: "r"(a), "r"((uint32_t)(b)) : "memory")
#define MBAR_ARRIVE(a) \
    asm volatile("mbarrier.arrive.shared.b64 _, [%0];" :: "r"((uint32_t)(a)) : "memory")
#define MBAR_WAIT(a, ph) do {                                                    \
    uint32_t _done = 0;                                                          \
    while (!_done)                                                               \
        asm volatile("{\n\t.reg .pred p;\n\t"                                    \
            "mbarrier.try_wait.parity.shared.b64 p, [%1], %2;\n\t"               \
            "selp.b32 %0, 1, 0, p;\n\t}"                                         \
            : "=r"(_done) : "r"((uint32_t)(a)), "r"((uint32_t)(ph)) : "memory"); \
    } while (0)
#define BULK_G2S(dst, src, bytes, mbar) \
    asm volatile("cp.async.bulk.shared::cluster.global.mbarrier::complete_tx::bytes " \
                 "[%0], [%1], %2, [%3];" \
                 :: "r"((uint32_t)(dst)), "l"(src), "r"((uint32_t)(bytes)), \
                    "r"((uint32_t)(mbar)) : "memory")

__device__ __forceinline__ uint32_t pack_h2(float lo, float hi) {
    half2 h = __floats2half2_rn(lo, hi);
    return *reinterpret_cast<uint32_t*>(&h);
}

// ---------------------------------------------------------------------------
// Staged prepass (unchanged from R14): one 128-thread block per 128x64 tile.
// Coalesced read -> fragment-order scatter into SMEM -> coalesced 16KB store.
// ---------------------------------------------------------------------------
__global__ void __launch_bounds__(128)
prepass_kernel(const int4* __restrict__ wp4,
               const float* __restrict__ centroids,
               const float* __restrict__ scales,
               const float* __restrict__ X, int M) {
    __shared__ uint32_t stg[TILE_U32];
    __shared__ float cent[16];
    const int bid = blockIdx.x;
    const int tid = threadIdx.x;

    if (bid < WTILES) {
        if (tid < 16) cent[tid] = centroids[tid];
        __syncthreads();
        const int ntile = bid >> 6;          // / NKT
        const int kt    = bid & (NKT - 1);

#pragma unroll
        for (int j = 0; j < 8; j++) {
            int f   = tid + j * 128;         // 0..1023
            int row = f >> 3;                // n within tile
            int q   = f & 7;                 // int4 within row-tile (8 k-elems)
            int o   = ntile * 128 + row;
            int4 w  = wp4[(size_t)o * (PACKED / 4) + kt * 8 + q];
            float s = scales[o * NBLK + kt];

            int b0 = w.x & 255, b1 = w.y & 255, b2 = w.z & 255, b3 = w.w & 255;
            float e0 = cent[b0 >> 4] * s, e1 = cent[b0 & 15] * s;
            float e2 = cent[b1 >> 4] * s, e3 = cent[b1 & 15] * s;
            float e4 = cent[b2 >> 4] * s, e5 = cent[b2 & 15] * s;
            float e6 = cent[b3 >> 4] * s, e7 = cent[b3 & 15] * s;

            int kp0 = q * 8;
            int kk  = kp0 >> 4;
            int hi  = (kp0 & 15) >> 3;
            int nf  = row >> 3;
            int l0  = (row & 7) * 4;
            uint32_t* b = stg + (kk * 16 + nf) * 64 + l0 * 2 + hi;
            b[0] = pack_h2(e0, e1);
            b[2] = pack_h2(e2, e3);
            b[4] = pack_h2(e4, e5);
            b[6] = pack_h2(e6, e7);
        }
        __syncthreads();
        uint4* dst = reinterpret_cast<uint4*>(
            g_Bt + (size_t)ntile * (NKT * TILE_U32) + (size_t)kt * TILE_U32);
        const uint4* src = reinterpret_cast<const uint4*>(stg);
#pragma unroll
        for (int j = 0; j < 8; j++) dst[tid + j * 128] = src[tid + j * 128];
    } else {
        const int b2    = bid - WTILES;
        const int mtile = b2 >> 6;
        const int kt    = b2 & (NKT - 1);

#pragma unroll
        for (int j = 0; j < 16; j++) {
            int f   = tid + j * 128;         // 0..2047
            int row = f >> 4;                // m within tile
            int c4  = f & 15;                // float4 within 64-k row
            float4 v = *reinterpret_cast<const float4*>(
                X + (size_t)(mtile * 128 + row) * IN_F + kt * 64 + c4 * 4);

            int kp = c4 * 4;
            int kk = kp >> 4, kw = kp & 15;
            int hi = kw >> 3;
            int c0 = (kw & 7) >> 1;
            int mf = row >> 4, rr = row & 15;
            int s  = ((rr >> 3) & 1) + 2 * hi;
            int l0 = (rr & 7) * 4 + c0;
            uint32_t* b = stg + (kk * 8 + mf) * 128 + l0 * 4 + s;
            b[0] = pack_h2(v.x, v.y);
            b[4] = pack_h2(v.z, v.w);        // next lane -> +4 u32
        }
        __syncthreads();
        uint4* dst = reinterpret_cast<uint4*>(
            g_At + (size_t)mtile * (NKT * TILE_U32) + (size_t)kt * TILE_U32);
        const uint4* src = reinterpret_cast<const uint4*>(stg);
#pragma unroll
        for (int j = 0; j < 8; j++) dst[tid + j * 128] = src[tid + j * 128];
    }
}

// ---------------------------------------------------------------------------
// GEMM: 128x128x64 tiles, 4 warps (2x2, warp tile 64x64), mma.sync fp16
// m16n8k16 fp32-accum, 2 CTA/SM. Bulk-async producer + full/empty mbarrier
// rings (no per-iteration __syncthreads -- warps drift within pipeline
// slack; WAR hazard handled by empty[s] with 128 arrivals).
// ---------------------------------------------------------------------------
__device__ __forceinline__ void mma_fp16(float* c, const uint32_t* a, const uint32_t* b) {
    asm volatile(
        "mma.sync.aligned.m16n8k16.row.col.f32.f16.f16.f32 "
        "{%0,%1,%2,%3}, {%4,%5,%6,%7}, {%8,%9}, {%0,%1,%2,%3};\n"
        : "+f"(c[0]), "+f"(c[1]), "+f"(c[2]), "+f"(c[3])
        : "r"(a[0]), "r"(a[1]), "r"(a[2]), "r"(a[3]),
          "r"(b[0]), "r"(b[1]));
}

__device__ __forceinline__ void load_frags(uint32_t a[4][4], uint32_t b[8][2],
                                           const uint32_t* A0, const uint32_t* B0,
                                           int kk, int wm, int wn, int lane) {
#pragma unroll
    for (int ma = 0; ma < 4; ma++) {
        const uint4 v = *reinterpret_cast<const uint4*>(
            A0 + (kk * 8 + wm * 4 + ma) * 128 + lane * 4);
        a[ma][0] = v.x; a[ma][1] = v.y; a[ma][2] = v.z; a[ma][3] = v.w;
    }
#pragma unroll
    for (int nb = 0; nb < 8; nb++) {
        const uint2 v = *reinterpret_cast<const uint2*>(
            B0 + (kk * 16 + wn * 8 + nb) * 64 + lane * 2);
        b[nb][0] = v.x; b[nb][1] = v.y;
    }
}

__global__ void __launch_bounds__(128, 2)
gemm_fp16_kernel(float* __restrict__ Out) {
    extern __shared__ uint32_t smem[];

    const int tid  = threadIdx.x;
    const int warp = tid >> 5;
    const int lane = tid & 31;
    const int wm = warp >> 1;              // 0..1 -> M offset wm*64
    const int wn = warp & 1;               // 0..1 -> N offset wn*64

    const uint32_t* Ag = g_At + (size_t)blockIdx.y * (NKT * TILE_U32);
    const uint32_t* Bg = g_Bt + (size_t)blockIdx.x * (NKT * TILE_U32);

    const uint32_t sbase = (uint32_t)__cvta_generic_to_shared(smem);
    const uint32_t mbF0  = sbase;                 // full[s]  at +s*8
    const uint32_t mbE0  = sbase + 64;            // empty[s] at +s*8
    const uint32_t st0   = sbase + SMEM_HDR;
    const uint32_t* stf  = smem + SMEM_HDR / 4;

    if (tid == 0) {
#pragma unroll
        for (int s = 0; s < STAGES; s++) {
            MBAR_INIT(mbF0 + s * 8, 1);
            MBAR_INIT(mbE0 + s * 8, 128);
        }
    }
    __syncthreads();

    if (tid == 0) {
#pragma unroll
        for (int p = 0; p < 2; p++) {
            MBAR_EXPECT_TX(mbF0 + p * 8, STAGE_BYTES);
            BULK_G2S(st0 + p * STAGE_BYTES,         Ag + (size_t)p * TILE_U32, 16384, mbF0 + p * 8);
            BULK_G2S(st0 + p * STAGE_BYTES + 16384, Bg + (size_t)p * TILE_U32, 16384, mbF0 + p * 8);
        }
    }

    float c[4][8][4];
#pragma unroll
    for (int i = 0; i < 4; i++)
#pragma unroll
        for (int j = 0; j < 8; j++)
#pragma unroll
            for (int k = 0; k < 4; k++) c[i][j][k] = 0.0f;

    uint32_t a[2][4][4];
    uint32_t b[2][8][2];

    for (int kt = 0; kt < NKT; kt++) {
        const int s = kt % STAGES;
        MBAR_WAIT(mbF0 + s * 8, (kt / STAGES) & 1);   // tile kt arrived

        const uint32_t* A0 = stf + (size_t)s * (STAGE_BYTES / 4);
        const uint32_t* B0 = A0 + TILE_U32;

        load_frags(a[0], b[0], A0, B0, 0, wm, wn, lane);

        if (tid == 0 && kt + 2 < NKT) {
            const int sn = (kt + 2) % STAGES;
            if (kt + 2 >= STAGES) {                   // not the first fill of sn
                const int u = (kt + 2) / STAGES;      // use index of stage sn
                MBAR_WAIT(mbE0 + sn * 8, (u - 1) & 1);  // prior use drained
            }
            MBAR_EXPECT_TX(mbF0 + sn * 8, STAGE_BYTES);
            BULK_G2S(st0 + sn * STAGE_BYTES,         Ag + (size_t)(kt + 2) * TILE_U32, 16384, mbF0 + sn * 8);
            BULK_G2S(st0 + sn * STAGE_BYTES + 16384, Bg + (size_t)(kt + 2) * TILE_U32, 16384, mbF0 + sn * 8);
        }

#pragma unroll
        for (int kk = 0; kk < 4; kk++) {
            const int cur = kk & 1;
            if (kk < 3)
                load_frags(a[cur ^ 1], b[cur ^ 1], A0, B0, kk + 1, wm, wn, lane);
#pragma unroll
            for (int ma = 0; ma < 4; ma++)
#pragma unroll
                for (int nb = 0; nb < 8; nb++)
                    mma_fp16(c[ma][nb], a[cur][ma], b[cur][nb]);
        }

        MBAR_ARRIVE(mbE0 + s * 8);   // this thread done reading stage s
    }

    // epilogue
    float* Og = Out + (size_t)blockIdx.y * BM * OUT_F + blockIdx.x * BN;
#pragma unroll
    for (int ma = 0; ma < 4; ma++) {
#pragma unroll
        for (int nb = 0; nb < 8; nb++) {
            int r  = wm * 64 + ma * 16 + (lane >> 2);
            int cc = wn * 64 + nb * 8 + 2 * (lane & 3);
            *reinterpret_cast<float2*>(&Og[(size_t)r * OUT_F + cc]) =
                make_float2(c[ma][nb][0], c[ma][nb][1]);
            *reinterpret_cast<float2*>(&Og[(size_t)(r + 8) * OUT_F + cc]) =
                make_float2(c[ma][nb][2], c[ma][nb][3]);
        }
    }
}

// ---------------------------------------------------------------------------
extern "C" void kernel_launch(void* const* d_in, const int* in_sizes, int n_in,
                              void* d_out, int out_size) {
    const float* x      = (const float*)d_in[0];   // [M, 4096] fp32
    const int*   wp     = (const int*)d_in[1];     // [4096, 2048] int32 bytes
    const float* cent   = (const float*)d_in[2];   // [16]
    const float* scales = (const float*)d_in[3];   // [4096, 64]
    float* out = (float*)d_out;

    const int M = in_sizes[0] / IN_F;              // 8192

    int xtiles = (M / BM) * NKT;                   // 4096
    prepass_kernel<<<WTILES + xtiles, 128>>>(
        reinterpret_cast<const int4*>(wp), cent, scales, x, M);

    cudaFuncSetAttribute(gemm_fp16_kernel,
                         cudaFuncAttributeMaxDynamicSharedMemorySize, SMEM_BYTES);
    dim3 grid(OUT_F / BN, M / BM);                 // (32, 64)
    gemm_fp16_kernel<<<grid, 128, SMEM_BYTES>>>(out);
}

// round 16
// speedup vs baseline: 1.1233x; 1.0041x over previous
#include <cuda_runtime.h>
#include <cuda_fp16.h>
#include <cstdint>

#define IN_F   4096
#define OUT_F  4096
#define PACKED (IN_F / 2)
#define NBLK   (IN_F / 64)

#define BM 128
#define BN 128
#define BK 64                        // fp16: 128x64 halfs = 16 KB per block
#define NKT (IN_F / BK)              // 64 k-tiles
#define TILE_U32 4096                // uint32s per operand block (16 KB)
#define STAGE_BYTES  32768           // A (16KB) + B (16KB)
#define STAGES 3
#define SMEM_HDR 1024
#define SMEM_BYTES (SMEM_HDR + STAGES * STAGE_BYTES)   // 99328 B -> 2 CTA/SM

#define WTILES ((OUT_F / BN) * NKT)  // 2048 weight tiles

// Fragment-ordered fp16 operand scratch (each uint32 = half2{k, k+1}).
// A block (128m x 64k): u32 idx = (kk*8 + mf)*128 + lane*4 + slot
//   lane = (rr&7)*4 + kpair, slot = (rr>>3) + 2*hi   (m=mf*16+rr, k=kk*16+hi*8+kpair*2)
// B block (128n x 64k): u32 idx = (kk*16 + nf)*64 + lane*2 + hi
//   lane = (n&7)*4 + kpair                            (n=nf*8+(n&7))
__device__ uint32_t g_At[(size_t)(8192 / BM) * NKT * TILE_U32];   // 67 MB
__device__ uint32_t g_Bt[(size_t)(OUT_F / BN) * NKT * TILE_U32];  // 33.5 MB

#define MBAR_INIT(a, c) \
    asm volatile("mbarrier.init.shared.b64 [%0], %1;" :: "r"(a), "r"((uint32_t)(c)) : "memory")
#define MBAR_EXPECT_TX(a, b) \
    asm volatile("mbarrier.arrive.expect_tx.shared.b64 _, [%0], %1;" :: "r"(a), "r"((uint32_t)(b)) : "memory")
#define MBAR_ARRIVE(a) \
    asm volatile("mbarrier.arrive.shared.b64 _, [%0];" :: "r"((uint32_t)(a)) : "memory")
#define MBAR_WAIT(a, ph) do {                                                    \
    uint32_t _done = 0;                                                          \
    while (!_done)                                                               \
        asm volatile("{\n\t.reg .pred p;\n\t"                                    \
            "mbarrier.try_wait.parity.shared.b64 p, [%1], %2;\n\t"               \
            "selp.b32 %0, 1, 0, p;\n\t}"                                         \
            : "=r"(_done) : "r"((uint32_t)(a)), "r"((uint32_t)(ph)) : "memory"); \
    } while (0)
#define BULK_G2S(dst, src, bytes, mbar) \
    asm volatile("cp.async.bulk.shared::cluster.global.mbarrier::complete_tx::bytes " \
                 "[%0], [%1], %2, [%3];" \
                 :: "r"((uint32_t)(dst)), "l"(src), "r"((uint32_t)(bytes)), \
                    "r"((uint32_t)(mbar)) : "memory")

__device__ __forceinline__ uint32_t pack_h2(float lo, float hi) {
    half2 h = __floats2half2_rn(lo, hi);
    return *reinterpret_cast<uint32_t*>(&h);
}

// ---------------------------------------------------------------------------
// Direct-store prepass (no SMEM staging): per-thread element grouping makes
// fragment-ordered output contiguous 32B runs -> perfectly coalesced st.128
// pairs. Blocks [0, WTILES): W dequant; rest: X retile.
// ---------------------------------------------------------------------------
__global__ void __launch_bounds__(128)
prepass_kernel(const int4* __restrict__ wp4,
               const float* __restrict__ centroids,
               const float* __restrict__ scales,
               const float* __restrict__ X, int M) {
    const int bid = blockIdx.x;
    const int tid = threadIdx.x;

    if (bid < WTILES) {
        __shared__ float cent[16];
        if (tid < 16) cent[tid] = centroids[tid];
        __syncthreads();

        const int ntile = bid >> 6;          // / NKT
        const int kt    = bid & (NKT - 1);
        const int o     = ntile * 128 + tid; // this thread's n-row
        const float s   = scales[o * NBLK + kt];
        const int4* wrow = wp4 + (size_t)o * (PACKED / 4) + kt * 8;

        uint4* dst = reinterpret_cast<uint4*>(
            g_Bt + (size_t)ntile * (NKT * TILE_U32) + (size_t)kt * TILE_U32);
        const int nf = tid >> 3;
        const int l8 = (tid & 7) * 8;        // u32 offset within nf block / 1

#pragma unroll
        for (int kk = 0; kk < 4; kk++) {
            int4 lo = wrow[kk * 2];          // k = kk*16 + 0..7   (hi=0)
            int4 hi = wrow[kk * 2 + 1];      // k = kk*16 + 8..15  (hi=1)

            #define DEQ(b) pack_h2(cent[((b) >> 4) & 15] * s, cent[(b) & 15] * s)
            uint4 u4a, u4b;
            u4a.x = DEQ(lo.x & 255); u4a.y = DEQ(hi.x & 255);   // kpair0: hi0, hi1
            u4a.z = DEQ(lo.y & 255); u4a.w = DEQ(hi.y & 255);   // kpair1
            u4b.x = DEQ(lo.z & 255); u4b.y = DEQ(hi.z & 255);   // kpair2
            u4b.z = DEQ(lo.w & 255); u4b.w = DEQ(hi.w & 255);   // kpair3
            #undef DEQ

            int off4 = ((kk * 16 + nf) * 64 + l8) >> 2;   // uint4 index
            dst[off4]     = u4a;
            dst[off4 + 1] = u4b;
        }
    } else {
        const int b2    = bid - WTILES;
        const int mtile = b2 >> 6;
        const int kt    = b2 & (NKT - 1);
        const int mf = tid >> 4;
        const int r  = (tid & 15) >> 1;      // row-within-16 (low 8)
        const int h  = tid & 1;              // k-quad within hi-half

        const float* xrow = X + (size_t)(mtile * 128 + mf * 16 + r) * IN_F
                              + kt * 64 + h * 4;
        uint4* dst = reinterpret_cast<uint4*>(
            g_At + (size_t)mtile * (NKT * TILE_U32) + (size_t)kt * TILE_U32);

#pragma unroll
        for (int kk = 0; kk < 4; kk++) {
            const float* p = xrow + kk * 16;
            float4 v0 = *reinterpret_cast<const float4*>(p);                 // row r,   hi0
            float4 v1 = *reinterpret_cast<const float4*>(p + 8 * IN_F);      // row r+8, hi0
            float4 v2 = *reinterpret_cast<const float4*>(p + 8);             // row r,   hi1
            float4 v3 = *reinterpret_cast<const float4*>(p + 8 * IN_F + 8);  // row r+8, hi1

            uint4 u4a, u4b;
            u4a.x = pack_h2(v0.x, v0.y); u4a.y = pack_h2(v1.x, v1.y);  // lane l0: slots 0..3
            u4a.z = pack_h2(v2.x, v2.y); u4a.w = pack_h2(v3.x, v3.y);
            u4b.x = pack_h2(v0.z, v0.w); u4b.y = pack_h2(v1.z, v1.w);  // lane l0+1
            u4b.z = pack_h2(v2.z, v2.w); u4b.w = pack_h2(v3.z, v3.w);

            int off4 = ((kk * 8 + mf) * 128 + r * 16 + h * 8) >> 2;    // uint4 index
            dst[off4]     = u4a;
            dst[off4 + 1] = u4b;
        }
    }
}

// ---------------------------------------------------------------------------
// GEMM (byte-identical to R15 best): 128x128x64 tiles, 4 warps (2x2, warp
// tile 64x64), mma.sync fp16 m16n8k16 fp32-accum, 2 CTA/SM. Bulk-async
// producer + full/empty mbarrier rings, register double-buffered fragments.
// ---------------------------------------------------------------------------
__device__ __forceinline__ void mma_fp16(float* c, const uint32_t* a, const uint32_t* b) {
    asm volatile(
        "mma.sync.aligned.m16n8k16.row.col.f32.f16.f16.f32 "
        "{%0,%1,%2,%3}, {%4,%5,%6,%7}, {%8,%9}, {%0,%1,%2,%3};\n"
        : "+f"(c[0]), "+f"(c[1]), "+f"(c[2]), "+f"(c[3])
        : "r"(a[0]), "r"(a[1]), "r"(a[2]), "r"(a[3]),
          "r"(b[0]), "r"(b[1]));
}

__device__ __forceinline__ void load_frags(uint32_t a[4][4], uint32_t b[8][2],
                                           const uint32_t* A0, const uint32_t* B0,
                                           int kk, int wm, int wn, int lane) {
#pragma unroll
    for (int ma = 0; ma < 4; ma++) {
        const uint4 v = *reinterpret_cast<const uint4*>(
            A0 + (kk * 8 + wm * 4 + ma) * 128 + lane * 4);
        a[ma][0] = v.x; a[ma][1] = v.y; a[ma][2] = v.z; a[ma][3] = v.w;
    }
#pragma unroll
    for (int nb = 0; nb < 8; nb++) {
        const uint2 v = *reinterpret_cast<const uint2*>(
            B0 + (kk * 16 + wn * 8 + nb) * 64 + lane * 2);
        b[nb][0] = v.x; b[nb][1] = v.y;
    }
}

__global__ void __launch_bounds__(128, 2)
gemm_fp16_kernel(float* __restrict__ Out) {
    extern __shared__ uint32_t smem[];

    const int tid  = threadIdx.x;
    const int warp = tid >> 5;
    const int lane = tid & 31;
    const int wm = warp >> 1;              // 0..1 -> M offset wm*64
    const int wn = warp & 1;               // 0..1 -> N offset wn*64

    const uint32_t* Ag = g_At + (size_t)blockIdx.y * (NKT * TILE_U32);
    const uint32_t* Bg = g_Bt + (size_t)blockIdx.x * (NKT * TILE_U32);

    const uint32_t sbase = (uint32_t)__cvta_generic_to_shared(smem);
    const uint32_t mbF0  = sbase;                 // full[s]  at +s*8
    const uint32_t mbE0  = sbase + 64;            // empty[s] at +s*8
    const uint32_t st0   = sbase + SMEM_HDR;
    const uint32_t* stf  = smem + SMEM_HDR / 4;

    if (tid == 0) {
#pragma unroll
        for (int s = 0; s < STAGES; s++) {
            MBAR_INIT(mbF0 + s * 8, 1);
            MBAR_INIT(mbE0 + s * 8, 128);
        }
    }
    __syncthreads();

    if (tid == 0) {
#pragma unroll
        for (int p = 0; p < 2; p++) {
            MBAR_EXPECT_TX(mbF0 + p * 8, STAGE_BYTES);
            BULK_G2S(st0 + p * STAGE_BYTES,         Ag + (size_t)p * TILE_U32, 16384, mbF0 + p * 8);
            BULK_G2S(st0 + p * STAGE_BYTES + 16384, Bg + (size_t)p * TILE_U32, 16384, mbF0 + p * 8);
        }
    }

    float c[4][8][4];
#pragma unroll
    for (int i = 0; i < 4; i++)
#pragma unroll
        for (int j = 0; j < 8; j++)
#pragma unroll
            for (int k = 0; k < 4; k++) c[i][j][k] = 0.0f;

    uint32_t a[2][4][4];
    uint32_t b[2][8][2];

    for (int kt = 0; kt < NKT; kt++) {
        const int s = kt % STAGES;
        MBAR_WAIT(mbF0 + s * 8, (kt / STAGES) & 1);   // tile kt arrived

        const uint32_t* A0 = stf + (size_t)s * (STAGE_BYTES / 4);
        const uint32_t* B0 = A0 + TILE_U32;

        load_frags(a[0], b[0], A0, B0, 0, wm, wn, lane);

        if (tid == 0 && kt + 2 < NKT) {
            const int sn = (kt + 2) % STAGES;
            if (kt + 2 >= STAGES) {                   // not the first fill of sn
                const int u = (kt + 2) / STAGES;      // use index of stage sn
                MBAR_WAIT(mbE0 + sn * 8, (u - 1) & 1);  // prior use drained
            }
            MBAR_EXPECT_TX(mbF0 + sn * 8, STAGE_BYTES);
            BULK_G2S(st0 + sn * STAGE_BYTES,         Ag + (size_t)(kt + 2) * TILE_U32, 16384, mbF0 + sn * 8);
            BULK_G2S(st0 + sn * STAGE_BYTES + 16384, Bg + (size_t)(kt + 2) * TILE_U32, 16384, mbF0 + sn * 8);
        }

#pragma unroll
        for (int kk = 0; kk < 4; kk++) {
            const int cur = kk & 1;
            if (kk < 3)
                load_frags(a[cur ^ 1], b[cur ^ 1], A0, B0, kk + 1, wm, wn, lane);
#pragma unroll
            for (int ma = 0; ma < 4; ma++)
#pragma unroll
                for (int nb = 0; nb < 8; nb++)
                    mma_fp16(c[ma][nb], a[cur][ma], b[cur][nb]);
        }

        MBAR_ARRIVE(mbE0 + s * 8);   // this thread done reading stage s
    }

    // epilogue
    float* Og = Out + (size_t)blockIdx.y * BM * OUT_F + blockIdx.x * BN;
#pragma unroll
    for (int ma = 0; ma < 4; ma++) {
#pragma unroll
        for (int nb = 0; nb < 8; nb++) {
            int r  = wm * 64 + ma * 16 + (lane >> 2);
            int cc = wn * 64 + nb * 8 + 2 * (lane & 3);
            *reinterpret_cast<float2*>(&Og[(size_t)r * OUT_F + cc]) =
                make_float2(c[ma][nb][0], c[ma][nb][1]);
            *reinterpret_cast<float2*>(&Og[(size_t)(r + 8) * OUT_F + cc]) =
                make_float2(c[ma][nb][2], c[ma][nb][3]);
        }
    }
}

// ---------------------------------------------------------------------------
extern "C" void kernel_launch(void* const* d_in, const int* in_sizes, int n_in,
                              void* d_out, int out_size) {
    const float* x      = (const float*)d_in[0];   // [M, 4096] fp32
    const int*   wp     = (const int*)d_in[1];     // [4096, 2048] int32 bytes
    const float* cent   = (const float*)d_in[2];   // [16]
    const float* scales = (const float*)d_in[3];   // [4096, 64]
    float* out = (float*)d_out;

    const int M = in_sizes[0] / IN_F;              // 8192

    int xtiles = (M / BM) * NKT;                   // 4096
    prepass_kernel<<<WTILES + xtiles, 128>>>(
        reinterpret_cast<const int4*>(wp), cent, scales, x, M);

    cudaFuncSetAttribute(gemm_fp16_kernel,
                         cudaFuncAttributeMaxDynamicSharedMemorySize, SMEM_BYTES);
    dim3 grid(OUT_F / BN, M / BM);                 // (32, 64)
    gemm_fp16_kernel<<<grid, 128, SMEM_BYTES>>>(out);
}